// round 14
// baseline (speedup 1.0000x reference)
#include <cuda_runtime.h>
#include <cuda_bf16.h>
#include <stdint.h>
#include <math.h>

#define NN   100000
#define NE   1600000
#define IND  256
#define HID  128
#define NL   4
#define OUTD 7
#define LN_EPS 1e-5f
#define SCAN_NB ((NN + 1023) / 1024)   // 98

// ---------------- scratch (device globals: no allocation allowed) ----------------
__device__ float g_h0[(size_t)NN * HID];
__device__ float g_ha[(size_t)NN * HID];
__device__ float g_hb[(size_t)NN * HID];
__device__ float g_s[NN];
__device__ float g_dis[NN];
__device__ int   g_cnt[NN];
__device__ int   g_cursor[NN];
__device__ int   g_rowptr[NN + 1];
__device__ int   g_colw[NE];
__device__ float g_eww[NE];
__device__ int   g_bsum[SCAN_NB + 32];
__device__ int   g_boff[SCAN_NB + 32];
__device__ __nv_bfloat16 g_wmodh[(size_t)NL * HID * HID];   // [l][n][k]
__device__ __nv_bfloat16 g_wmodl[(size_t)NL * HID * HID];
__device__ __nv_bfloat16 g_wprojh[(size_t)HID * IND];       // [n][k]
__device__ __nv_bfloat16 g_wprojl[(size_t)HID * IND];

// ---------------- helpers ----------------
__device__ __forceinline__ void bf16split(float v, __nv_bfloat16& hi, __nv_bfloat16& lo) {
    hi = __float2bfloat16(v);
    lo = __float2bfloat16(v - __bfloat162float(hi));
}

// split a float2 (two consecutive k values) into packed bf16x2 hi and lo words
__device__ __forceinline__ void split2(float2 p, unsigned int& hi, unsigned int& lo) {
    __nv_bfloat16 h0, l0, h1, l1;
    bf16split(p.x, h0, l0);
    bf16split(p.y, h1, l1);
    __nv_bfloat162 hp = __halves2bfloat162(h0, h1);
    __nv_bfloat162 lp = __halves2bfloat162(l0, l1);
    hi = *reinterpret_cast<unsigned int*>(&hp);
    lo = *reinterpret_cast<unsigned int*>(&lp);
}

__device__ __forceinline__ void mma_bf16(float* d, const unsigned int* a, const unsigned int* b) {
    asm volatile(
        "mma.sync.aligned.m16n8k16.row.col.f32.bf16.bf16.f32 "
        "{%0,%1,%2,%3}, {%4,%5,%6,%7}, {%8,%9}, {%0,%1,%2,%3};\n"
        : "+f"(d[0]), "+f"(d[1]), "+f"(d[2]), "+f"(d[3])
        : "r"(a[0]), "r"(a[1]), "r"(a[2]), "r"(a[3]), "r"(b[0]), "r"(b[1]));
}

__device__ __forceinline__ void cp_async16(unsigned int smem_addr, const void* gptr, int src_sz) {
    asm volatile("cp.async.cg.shared.global [%0], [%1], 16, %2;\n"
                 :: "r"(smem_addr), "l"(gptr), "r"(src_sz));
}

// ---------------- weight prep ----------------
// W_proj [k][n] -> transposed bf16 planes [n][k]
__global__ void k_prepproj(const float* __restrict__ wp,
                           __nv_bfloat16* __restrict__ wh, __nv_bfloat16* __restrict__ wl) {
    int i = blockIdx.x * blockDim.x + threadIdx.x;
    if (i < IND * HID) {
        int n = i / IND, k = i - n * IND;
        float v = wp[(size_t)k * HID + n];
        __nv_bfloat16 hi, lo;
        bf16split(v, hi, lo);
        wh[i] = hi; wl[i] = lo;
    }
}

// W'[l] = theta_l*conv_w[l] + (1-theta_l)*I, transposed bf16 planes [l][n][k]
__global__ void k_prepw(const float* __restrict__ conv_w,
                        __nv_bfloat16* __restrict__ wh, __nv_bfloat16* __restrict__ wl) {
    int i = blockIdx.x * blockDim.x + threadIdx.x;
    if (i < NL * HID * HID) {
        int l = i / (HID * HID);
        int rc = i - l * (HID * HID);
        int n = rc >> 7, k = rc & 127;
        float theta = 0.5f / (float)(l + 1);
        float v = theta * conv_w[(size_t)l * HID * HID + k * HID + n];
        if (k == n) v += 1.0f - theta;
        __nv_bfloat16 hi, lo;
        bf16split(v, hi, lo);
        wh[i] = hi; wl[i] = lo;
    }
}

// ---------------- graph preprocessing ----------------
__global__ void k_zero(int* cnt, int* cursor) {
    int i = blockIdx.x * blockDim.x + threadIdx.x;
    if (i < NN) { cnt[i] = 0; cursor[i] = 0; }
}

__global__ void k_hist(const int* __restrict__ row, int* __restrict__ cnt) {
    int i = blockIdx.x * blockDim.x + threadIdx.x;
    if (i < NE) atomicAdd(&cnt[row[i]], 1);
}

__global__ void k_dis(const int* __restrict__ cnt, float* __restrict__ dis) {
    int i = blockIdx.x * blockDim.x + threadIdx.x;
    if (i < NN) {
        int c = cnt[i];
        float dg = (c == 0) ? 1.0f : (float)c;
        dis[i] = rsqrtf(dg);
    }
}

__global__ void k_bsum(const int* __restrict__ cnt, int* __restrict__ bsum) {
    __shared__ int sm[256];
    const int b = blockIdx.x, t = threadIdx.x;
    int base = b * 1024;
    int s = 0;
    #pragma unroll
    for (int q = 0; q < 4; q++) {
        int i = base + q * 256 + t;
        if (i < NN) s += cnt[i];
    }
    sm[t] = s;
    __syncthreads();
    for (int off = 128; off > 0; off >>= 1) {
        if (t < off) sm[t] += sm[t + off];
        __syncthreads();
    }
    if (t == 0) bsum[b] = sm[0];
}

__global__ void k_bscan(const int* __restrict__ bsum, int* __restrict__ boff) {
    __shared__ int sm[128];
    int t = threadIdx.x;
    sm[t] = (t < SCAN_NB) ? bsum[t] : 0;
    __syncthreads();
    for (int off = 1; off < 128; off <<= 1) {
        int v = (t >= off) ? sm[t - off] : 0;
        __syncthreads();
        sm[t] += v;
        __syncthreads();
    }
    if (t < SCAN_NB) boff[t] = (t == 0) ? 0 : sm[t - 1];
}

__global__ void k_rowptr(const int* __restrict__ cnt, const int* __restrict__ boff,
                         int* __restrict__ rowptr) {
    __shared__ int sm[256];
    const int b = blockIdx.x, t = threadIdx.x;
    int base = b * 1024;
    int vals[4];
    int s = 0;
    #pragma unroll
    for (int q = 0; q < 4; q++) {
        int i = base + t * 4 + q;
        vals[q] = (i < NN) ? cnt[i] : 0;
        s += vals[q];
    }
    sm[t] = s;
    __syncthreads();
    for (int off = 1; off < 256; off <<= 1) {
        int v = (t >= off) ? sm[t - off] : 0;
        __syncthreads();
        sm[t] += v;
        __syncthreads();
    }
    int run = boff[b] + ((t == 0) ? 0 : sm[t - 1]);
    #pragma unroll
    for (int q = 0; q < 4; q++) {
        int i = base + t * 4 + q;
        if (i < NN) rowptr[i] = run;
        run += vals[q];
    }
    if (b == 0 && t == 0) rowptr[NN] = NE;
}

__global__ void k_scatter(const int* __restrict__ row, const int* __restrict__ col,
                          const int* __restrict__ rowptr, int* __restrict__ cursor,
                          const float* __restrict__ dis,
                          int* __restrict__ colw, float* __restrict__ eww) {
    int i = blockIdx.x * blockDim.x + threadIdx.x;
    if (i < NE) {
        int r = row[i], c = col[i];
        int pos = rowptr[r] + atomicAdd(&cursor[r], 1);
        colw[pos] = c;
        eww[pos] = dis[r] * dis[c];
    }
}

// ---------------- fused [SpMM+blend] -> 3xBF16 GEMM -> LN+gate ----------------
// MODE 0 (proj): out = LN(x @ Wp + bias); A = fp32 x streamed via cp.async,
//                split to bf16 hi/lo at fragment load.
// MODE 1 (layer): gather phase builds A = (1-s)*A_norm@hprev + s*h0 for this
//                block's 128 rows into a full-K fp32 smem tile; then
//                out = LN(relu(A @ W')) with split-at-fragment-load.
// s_out = sigmoid(out @ q_w + q_b - 1)   (gate for the NEXT layer)
#define KC 16                 // K per chunk = one m16n8k16
#define PITCH 24              // W bf16 row pitch per chunk
#define APF 20                // proj fp32 A chunk row pitch
#define AFP 132               // fused fp32 A full-K row pitch
#define PLANE_B (128 * PITCH * 2)       // 6144 B per W plane chunk-buffer
#define APLANE_B (128 * APF * 4)        // 10240 B per proj A chunk-buffer
#define O_A 0                            // 128*AFP*4 = 67584 (proj uses 2*APLANE_B of it)
#define O_BH 67584                       // 2 bufs * 6144
#define O_BL (67584 + 12288)
#define O_FLT (67584 + 24576)            // 92160
#define SMEM_BYTES (O_FLT + (256 * 3 + 512) * 4)   // 97280

template<int K, int MODE>
__launch_bounds__(256, 2)
__global__ void k_gemm_tc(const float* __restrict__ Ax,
                          const float* __restrict__ hprev, const float* __restrict__ h0v,
                          const float* __restrict__ sgate,
                          const int* __restrict__ rowptr, const int* __restrict__ colw,
                          const float* __restrict__ eww,
                          const __nv_bfloat16* __restrict__ Wh, const __nv_bfloat16* __restrict__ Wl,
                          const float* __restrict__ bias,
                          const float* __restrict__ gamma, const float* __restrict__ beta,
                          const float* __restrict__ qw, const float* __restrict__ qb,
                          float* __restrict__ out, float* __restrict__ s_out) {
    constexpr int NK = K / KC;
    extern __shared__ char smc[];
    float* fl  = (float*)(smc + O_FLT);
    float* stS = fl;
    float* stQ = fl + 256;
    float* stG = fl + 512;
    float* gsm = fl + 768;
    float* besm = gsm + 128;
    float* qsm  = gsm + 256;
    float* bism = gsm + 384;

    const int tid = threadIdx.x;
    const int lane = tid & 31;
    const int warp = tid >> 5;
    const int wm = warp & 3;          // rows wm*32
    const int wn = warp >> 2;         // cols wn*64
    const int g  = lane >> 2;
    const int t  = lane & 3;
    const int r0 = blockIdx.x * 128;
    const float qbv = qb[0];

    if (tid < 128) {
        gsm[tid]  = gamma[tid];
        besm[tid] = beta[tid];
        qsm[tid]  = qw[tid];
        bism[tid] = (MODE == 0) ? bias[tid] : 0.f;
    }

    // cp.async mappings
    const int crow = tid >> 1, chalf = tid & 1;   // W planes: 1 chunk/thread/plane
    const int xrow0 = tid >> 2, xq0 = tid & 3;    // proj fp32 A: 2 chunks/thread
    const int xrow1 = (tid + 256) >> 2, xq1 = (tid + 256) & 3;

    auto issue = [&](int kt, int buf) {
        unsigned int d;
        const int dof = crow * (PITCH * 2) + chalf * 16;
        const int soff = kt + chalf * 8;
        d = (unsigned int)__cvta_generic_to_shared(smc + O_BH + buf * PLANE_B + dof);
        cp_async16(d, Wh + (size_t)crow * K + soff, 16);
        d = (unsigned int)__cvta_generic_to_shared(smc + O_BL + buf * PLANE_B + dof);
        cp_async16(d, Wl + (size_t)crow * K + soff, 16);
        if (MODE == 0) {
            int sz0 = (r0 + xrow0 < NN) ? 16 : 0;
            int sz1 = (r0 + xrow1 < NN) ? 16 : 0;
            d = (unsigned int)__cvta_generic_to_shared(smc + O_A + buf * APLANE_B + xrow0 * (APF * 4) + xq0 * 16);
            cp_async16(d, Ax + (size_t)(r0 + xrow0) * K + kt + xq0 * 4, sz0);
            d = (unsigned int)__cvta_generic_to_shared(smc + O_A + buf * APLANE_B + xrow1 * (APF * 4) + xq1 * 16);
            cp_async16(d, Ax + (size_t)(r0 + xrow1) * K + kt + xq1 * 4, sz1);
        }
        asm volatile("cp.async.commit_group;\n");
    };

    float acc[2][8][4];
    #pragma unroll
    for (int mt = 0; mt < 2; mt++)
        #pragma unroll
        for (int nt = 0; nt < 8; nt++)
            #pragma unroll
            for (int q = 0; q < 4; q++) acc[mt][nt][q] = 0.f;

    issue(0, 0);

    // -------- gather phase (MODE 1): build fp32 A tile in smem --------
    if (MODE == 1) {
        float* Af = (float*)(smc + O_A);
        for (int rr = warp; rr < 128; rr += 8) {
            int r = r0 + rr;
            if (r < NN) {
                int start = rowptr[r], end = rowptr[r + 1];
                float ax = 0.f, ay = 0.f, az = 0.f, aw = 0.f;
                for (int e0 = start; e0 < end; e0 += 32) {
                    int n = end - e0; if (n > 32) n = 32;
                    int c = 0; float w = 0.f;
                    if (lane < n) { c = colw[e0 + lane]; w = eww[e0 + lane]; }
                    for (int j = 0; j < n; j++) {
                        int cj   = __shfl_sync(0xffffffffu, c, j);
                        float wj = __shfl_sync(0xffffffffu, w, j);
                        const float4 hv = *reinterpret_cast<const float4*>(hprev + (size_t)cj * HID + lane * 4);
                        ax += wj * hv.x; ay += wj * hv.y; az += wj * hv.z; aw += wj * hv.w;
                    }
                }
                float sr = sgate[r];
                float om = 1.0f - sr;
                const float4 h04 = *reinterpret_cast<const float4*>(h0v + (size_t)r * HID + lane * 4);
                float4 o;
                o.x = om * ax + sr * h04.x;
                o.y = om * ay + sr * h04.y;
                o.z = om * az + sr * h04.z;
                o.w = om * aw + sr * h04.w;
                *reinterpret_cast<float4*>(&Af[rr * AFP + lane * 4]) = o;
            } else {
                *reinterpret_cast<float4*>(&Af[rr * AFP + lane * 4]) = make_float4(0.f, 0.f, 0.f, 0.f);
            }
        }
    }

    // -------- mainloop: one __syncthreads per K-chunk --------
    #pragma unroll
    for (int i = 0; i < NK; i++) {
        asm volatile("cp.async.wait_group 0;\n");
        __syncthreads();
        if (i + 1 < NK) issue((i + 1) * KC, (i + 1) & 1);

        const float* af32 = (MODE == 0)
            ? (const float*)(smc + O_A + (i & 1) * APLANE_B)
            : (const float*)(smc + O_A);
        const int apitch = (MODE == 0) ? APF : AFP;
        const int kof = (MODE == 0) ? 0 : i * KC;

        unsigned int afh[2][4], afl[2][4];
        #pragma unroll
        for (int mt = 0; mt < 2; mt++) {
            const int rA = (wm * 32 + mt * 16 + g) * apitch + kof;
            const int rB = rA + 8 * apitch;
            float2 p0 = *(const float2*)&af32[rA + 2 * t];
            float2 p1 = *(const float2*)&af32[rB + 2 * t];
            float2 p2 = *(const float2*)&af32[rA + 8 + 2 * t];
            float2 p3 = *(const float2*)&af32[rB + 8 + 2 * t];
            split2(p0, afh[mt][0], afl[mt][0]);
            split2(p1, afh[mt][1], afl[mt][1]);
            split2(p2, afh[mt][2], afl[mt][2]);
            split2(p3, afh[mt][3], afl[mt][3]);
        }
        const int bo = (i & 1) * PLANE_B;
        const __nv_bfloat16* bsh = (const __nv_bfloat16*)(smc + O_BH + bo);
        const __nv_bfloat16* bsl = (const __nv_bfloat16*)(smc + O_BL + bo);
        unsigned int bfh[8][2], bfl[8][2];
        #pragma unroll
        for (int nt = 0; nt < 8; nt++) {
            const int nb = (wn * 64 + nt * 8 + g) * PITCH;
            bfh[nt][0] = *(const unsigned int*)&bsh[nb + 2 * t];
            bfh[nt][1] = *(const unsigned int*)&bsh[nb + 8 + 2 * t];
            bfl[nt][0] = *(const unsigned int*)&bsl[nb + 2 * t];
            bfl[nt][1] = *(const unsigned int*)&bsl[nb + 8 + 2 * t];
        }
        #pragma unroll
        for (int mt = 0; mt < 2; mt++)
            #pragma unroll
            for (int nt = 0; nt < 8; nt++) {
                mma_bf16(acc[mt][nt], afh[mt], bfl[nt]);   // hi*lo
                mma_bf16(acc[mt][nt], afl[mt], bfh[nt]);   // lo*hi
                mma_bf16(acc[mt][nt], afh[mt], bfh[nt]);   // hi*hi (largest last)
            }
    }
    __syncthreads();

    // ---- epilogue in fragment layout ----
    float vsum[2][2], vsq[2][2];
    #pragma unroll
    for (int mt = 0; mt < 2; mt++)
        #pragma unroll
        for (int hf = 0; hf < 2; hf++) { vsum[mt][hf] = 0.f; vsq[mt][hf] = 0.f; }

    #pragma unroll
    for (int mt = 0; mt < 2; mt++)
        #pragma unroll
        for (int nt = 0; nt < 8; nt++) {
            int c0 = wn * 64 + nt * 8 + 2 * t;
            #pragma unroll
            for (int q = 0; q < 4; q++) {
                int col = c0 + (q & 1);
                float v = acc[mt][nt][q];
                v = (MODE == 0) ? (v + bism[col]) : fmaxf(v, 0.f);
                acc[mt][nt][q] = v;
                int hf = q >> 1;
                vsum[mt][hf] += v;
                vsq[mt][hf]  += v * v;
            }
        }

    #pragma unroll
    for (int off = 1; off <= 2; off <<= 1)
        #pragma unroll
        for (int mt = 0; mt < 2; mt++)
            #pragma unroll
            for (int hf = 0; hf < 2; hf++) {
                vsum[mt][hf] += __shfl_xor_sync(0xffffffffu, vsum[mt][hf], off);
                vsq[mt][hf]  += __shfl_xor_sync(0xffffffffu, vsq[mt][hf],  off);
            }

    if (t == 0) {
        #pragma unroll
        for (int mt = 0; mt < 2; mt++)
            #pragma unroll
            for (int hf = 0; hf < 2; hf++) {
                int rl = wm * 32 + mt * 16 + g + hf * 8;
                stS[wn * 128 + rl] = vsum[mt][hf];
                stQ[wn * 128 + rl] = vsq[mt][hf];
            }
    }
    __syncthreads();

    float mu[2][2], rs[2][2];
    #pragma unroll
    for (int mt = 0; mt < 2; mt++)
        #pragma unroll
        for (int hf = 0; hf < 2; hf++) {
            int rl = wm * 32 + mt * 16 + g + hf * 8;
            float sm = stS[rl] + stS[128 + rl];
            float sq = stQ[rl] + stQ[128 + rl];
            float m = sm * (1.0f / 128.0f);
            float var = sq * (1.0f / 128.0f) - m * m;
            var = fmaxf(var, 0.f);
            mu[mt][hf] = m;
            rs[mt][hf] = rsqrtf(var + LN_EPS);
        }

    float gp[2][2];
    #pragma unroll
    for (int mt = 0; mt < 2; mt++)
        #pragma unroll
        for (int hf = 0; hf < 2; hf++) gp[mt][hf] = 0.f;

    #pragma unroll
    for (int mt = 0; mt < 2; mt++)
        #pragma unroll
        for (int nt = 0; nt < 8; nt++) {
            int c0 = wn * 64 + nt * 8 + 2 * t;
            #pragma unroll
            for (int hf = 0; hf < 2; hf++) {
                float o0 = gsm[c0]     * (acc[mt][nt][hf * 2 + 0] - mu[mt][hf]) * rs[mt][hf] + besm[c0];
                float o1 = gsm[c0 + 1] * (acc[mt][nt][hf * 2 + 1] - mu[mt][hf]) * rs[mt][hf] + besm[c0 + 1];
                gp[mt][hf] += o0 * qsm[c0] + o1 * qsm[c0 + 1];
                int r = r0 + wm * 32 + mt * 16 + g + hf * 8;
                if (r < NN) {
                    float2 o2 = make_float2(o0, o1);
                    *reinterpret_cast<float2*>(out + (size_t)r * HID + c0) = o2;
                }
            }
        }

    #pragma unroll
    for (int off = 1; off <= 2; off <<= 1)
        #pragma unroll
        for (int mt = 0; mt < 2; mt++)
            #pragma unroll
            for (int hf = 0; hf < 2; hf++)
                gp[mt][hf] += __shfl_xor_sync(0xffffffffu, gp[mt][hf], off);

    if (t == 0) {
        #pragma unroll
        for (int mt = 0; mt < 2; mt++)
            #pragma unroll
            for (int hf = 0; hf < 2; hf++) {
                int rl = wm * 32 + mt * 16 + g + hf * 8;
                stG[wn * 128 + rl] = gp[mt][hf];
            }
    }
    __syncthreads();

    if (wn == 0 && t == 0) {
        #pragma unroll
        for (int mt = 0; mt < 2; mt++)
            #pragma unroll
            for (int hf = 0; hf < 2; hf++) {
                int rl = wm * 32 + mt * 16 + g + hf * 8;
                int r = r0 + rl;
                if (r < NN) {
                    float z = stG[rl] + stG[128 + rl] + qbv - 1.0f;
                    s_out[r] = 1.0f / (1.0f + expf(-z));
                }
            }
    }
}

// ---------------- classifier: out = h @ cls_w + cls_b ----------------
__global__ void k_cls(const float* __restrict__ h, const float* __restrict__ cw,
                      const float* __restrict__ cb, float* __restrict__ out) {
    __shared__ float wsm[HID * OUTD];
    __shared__ float bsm[OUTD];
    for (int i = threadIdx.x; i < HID * OUTD; i += blockDim.x) wsm[i] = cw[i];
    if (threadIdx.x < OUTD) bsm[threadIdx.x] = cb[threadIdx.x];
    __syncthreads();

    int wid = (blockIdx.x * blockDim.x + threadIdx.x) >> 5;
    int lane = threadIdx.x & 31;
    if (wid >= NN) return;
    const float4 hv = *reinterpret_cast<const float4*>(h + (size_t)wid * HID + lane * 4);
    float hvv[4] = {hv.x, hv.y, hv.z, hv.w};
    float p[OUTD];
    #pragma unroll
    for (int j = 0; j < OUTD; j++) p[j] = 0.f;
    #pragma unroll
    for (int tq = 0; tq < 4; tq++) {
        int k = lane * 4 + tq;
        #pragma unroll
        for (int j = 0; j < OUTD; j++) p[j] += hvv[tq] * wsm[k * OUTD + j];
    }
    #pragma unroll
    for (int off = 16; off > 0; off >>= 1)
        #pragma unroll
        for (int j = 0; j < OUTD; j++) p[j] += __shfl_xor_sync(0xffffffffu, p[j], off);
    if (lane == 0) {
        #pragma unroll
        for (int j = 0; j < OUTD; j++) out[(size_t)wid * OUTD + j] = p[j] + bsm[j];
    }
}

// ---------------- launch ----------------
extern "C" void kernel_launch(void* const* d_in, const int* in_sizes, int n_in,
                              void* d_out, int out_size) {
    const float* x      = (const float*)d_in[0];
    const int*   ei     = (const int*)d_in[1];
    const float* W_proj = (const float*)d_in[2];
    const float* b_proj = (const float*)d_in[3];
    const float* gamma  = (const float*)d_in[4];
    const float* beta   = (const float*)d_in[5];
    const float* q_w    = (const float*)d_in[6];
    const float* q_b    = (const float*)d_in[7];
    const float* conv_w = (const float*)d_in[8];
    const float* cls_w  = (const float*)d_in[9];
    const float* cls_b  = (const float*)d_in[10];
    float* out = (float*)d_out;

    const int* row = ei;
    const int* col = ei + NE;

    float *h0, *ha, *hb, *s, *dis, *eww;
    __nv_bfloat16 *wmh, *wml, *wph, *wpl;
    int *cnt, *cursor, *rowptr, *colw, *bsum, *boff;
    cudaGetSymbolAddress((void**)&h0, g_h0);
    cudaGetSymbolAddress((void**)&ha, g_ha);
    cudaGetSymbolAddress((void**)&hb, g_hb);
    cudaGetSymbolAddress((void**)&s, g_s);
    cudaGetSymbolAddress((void**)&dis, g_dis);
    cudaGetSymbolAddress((void**)&cnt, g_cnt);
    cudaGetSymbolAddress((void**)&cursor, g_cursor);
    cudaGetSymbolAddress((void**)&rowptr, g_rowptr);
    cudaGetSymbolAddress((void**)&colw, g_colw);
    cudaGetSymbolAddress((void**)&eww, g_eww);
    cudaGetSymbolAddress((void**)&bsum, g_bsum);
    cudaGetSymbolAddress((void**)&boff, g_boff);
    cudaGetSymbolAddress((void**)&wmh, g_wmodh);
    cudaGetSymbolAddress((void**)&wml, g_wmodl);
    cudaGetSymbolAddress((void**)&wph, g_wprojh);
    cudaGetSymbolAddress((void**)&wpl, g_wprojl);

    cudaFuncSetAttribute(k_gemm_tc<IND, 0>,
                         cudaFuncAttributeMaxDynamicSharedMemorySize, SMEM_BYTES);
    cudaFuncSetAttribute(k_gemm_tc<HID, 1>,
                         cudaFuncAttributeMaxDynamicSharedMemorySize, SMEM_BYTES);

    const int TB = 256;
    const int gN  = (NN + TB - 1) / TB;
    const int gE  = (NE + TB - 1) / TB;
    const int gW  = (NN * 32 + TB - 1) / TB;    // warp-per-row grids
    const int gG  = (NN + 127) / 128;           // gemm grid (782)

    // Fork a side stream so the CSR build overlaps the proj GEMM chain.
    // (host-side objects only; intentionally retained — see R12 notes)
    cudaStream_t s1;
    cudaStreamCreateWithFlags(&s1, cudaStreamNonBlocking);
    cudaEvent_t evF, evJ;
    cudaEventCreateWithFlags(&evF, cudaEventDisableTiming);
    cudaEventCreateWithFlags(&evJ, cudaEventDisableTiming);

    cudaEventRecord(evF, 0);
    cudaStreamWaitEvent(s1, evF, 0);

    // branch B (side stream): CSR build + layer-weight prep
    k_zero<<<gN, TB, 0, s1>>>(cnt, cursor);                                   // 0
    k_hist<<<gE, TB, 0, s1>>>(row, cnt);                                      // 1
    // branch A (main stream): proj weights + proj GEMM (in-kernel x split)
    k_prepproj<<<(IND * HID + 255) / 256, 256>>>(W_proj, wph, wpl);           // 2
    k_gemm_tc<IND, 0><<<gG, 256, SMEM_BYTES>>>(x, nullptr, nullptr, nullptr,
                                               nullptr, nullptr, nullptr,
                                               wph, wpl, b_proj,
                                               gamma, beta, q_w, q_b, h0, s); // 3
    k_dis<<<gN, TB, 0, s1>>>(cnt, dis);                                       // 4
    k_bsum<<<SCAN_NB, 256, 0, s1>>>(cnt, bsum);                               // 5
    k_bscan<<<1, 128, 0, s1>>>(bsum, boff);                                   // 6
    k_rowptr<<<SCAN_NB, 256, 0, s1>>>(cnt, boff, rowptr);                     // 7
    k_scatter<<<gE, TB, 0, s1>>>(row, col, rowptr, cursor, dis, colw, eww);   // 8
    k_prepw<<<(NL * HID * HID + 255) / 256, 256, 0, s1>>>(conv_w, wmh, wml);  // 9

    cudaEventRecord(evJ, s1);
    cudaStreamWaitEvent(0, evJ, 0);

    const float* hprev = h0;
    float* hnext = ha;
    for (int i = 0; i < NL; i++) {
        k_gemm_tc<HID, 1><<<gG, 256, SMEM_BYTES>>>(nullptr, hprev, h0, s,
                                                   rowptr, colw, eww,
                                                   wmh + (size_t)i * HID * HID,
                                                   wml + (size_t)i * HID * HID,
                                                   nullptr, gamma, beta, q_w, q_b,
                                                   hnext, s);
        hprev = hnext;
        hnext = (hnext == ha) ? hb : ha;
    }

    k_cls<<<gW, TB>>>(hprev, cls_w, cls_b, out);
}

// round 15
// speedup vs baseline: 1.2357x; 1.2357x over previous
#include <cuda_runtime.h>
#include <cuda_bf16.h>
#include <stdint.h>
#include <math.h>

#define NN   100000
#define NE   1600000
#define IND  256
#define HID  128
#define NL   4
#define OUTD 7
#define LN_EPS 1e-5f
#define SCAN_NB ((NN + 1023) / 1024)   // 98

// ---------------- scratch (device globals: no allocation allowed) ----------------
__device__ float g_h0[(size_t)NN * HID];
__device__ float g_h [(size_t)NN * HID];
__device__ __nv_bfloat16 g_suph[(size_t)NN * HID];
__device__ __nv_bfloat16 g_supl[(size_t)NN * HID];
__device__ float g_s[NN];
__device__ float g_dis[NN];
__device__ int   g_cnt[NN];
__device__ int   g_cursor[NN];
__device__ int   g_rowptr[NN + 1];
__device__ int   g_colw[NE];
__device__ float g_eww[NE];
__device__ int   g_bsum[SCAN_NB + 32];
__device__ int   g_boff[SCAN_NB + 32];
__device__ __nv_bfloat16 g_wmodh[(size_t)NL * HID * HID];   // [l][n][k]
__device__ __nv_bfloat16 g_wmodl[(size_t)NL * HID * HID];
__device__ __nv_bfloat16 g_wprojh[(size_t)HID * IND];       // [n][k]
__device__ __nv_bfloat16 g_wprojl[(size_t)HID * IND];

// ---------------- helpers ----------------
__device__ __forceinline__ void bf16split(float v, __nv_bfloat16& hi, __nv_bfloat16& lo) {
    hi = __float2bfloat16(v);
    lo = __float2bfloat16(v - __bfloat162float(hi));
}

// split a float2 (two consecutive k values) into packed bf16x2 hi and lo words
__device__ __forceinline__ void split2(float2 p, unsigned int& hi, unsigned int& lo) {
    __nv_bfloat16 h0, l0, h1, l1;
    bf16split(p.x, h0, l0);
    bf16split(p.y, h1, l1);
    __nv_bfloat162 hp = __halves2bfloat162(h0, h1);
    __nv_bfloat162 lp = __halves2bfloat162(l0, l1);
    hi = *reinterpret_cast<unsigned int*>(&hp);
    lo = *reinterpret_cast<unsigned int*>(&lp);
}

__device__ __forceinline__ void mma_bf16(float* d, const unsigned int* a, const unsigned int* b) {
    asm volatile(
        "mma.sync.aligned.m16n8k16.row.col.f32.bf16.bf16.f32 "
        "{%0,%1,%2,%3}, {%4,%5,%6,%7}, {%8,%9}, {%0,%1,%2,%3};\n"
        : "+f"(d[0]), "+f"(d[1]), "+f"(d[2]), "+f"(d[3])
        : "r"(a[0]), "r"(a[1]), "r"(a[2]), "r"(a[3]), "r"(b[0]), "r"(b[1]));
}

__device__ __forceinline__ void cp_async16(unsigned int smem_addr, const void* gptr, int src_sz) {
    asm volatile("cp.async.cg.shared.global [%0], [%1], 16, %2;\n"
                 :: "r"(smem_addr), "l"(gptr), "r"(src_sz));
}

// ---------------- weight prep ----------------
// W_proj [k][n] -> transposed bf16 planes [n][k]
__global__ void k_prepproj(const float* __restrict__ wp,
                           __nv_bfloat16* __restrict__ wh, __nv_bfloat16* __restrict__ wl) {
    int i = blockIdx.x * blockDim.x + threadIdx.x;
    if (i < IND * HID) {
        int n = i / IND, k = i - n * IND;
        float v = wp[(size_t)k * HID + n];
        __nv_bfloat16 hi, lo;
        bf16split(v, hi, lo);
        wh[i] = hi; wl[i] = lo;
    }
}

// W'[l] = theta_l*conv_w[l] + (1-theta_l)*I, transposed bf16 planes [l][n][k]
__global__ void k_prepw(const float* __restrict__ conv_w,
                        __nv_bfloat16* __restrict__ wh, __nv_bfloat16* __restrict__ wl) {
    int i = blockIdx.x * blockDim.x + threadIdx.x;
    if (i < NL * HID * HID) {
        int l = i / (HID * HID);
        int rc = i - l * (HID * HID);
        int n = rc >> 7, k = rc & 127;
        float theta = 0.5f / (float)(l + 1);
        float v = theta * conv_w[(size_t)l * HID * HID + k * HID + n];
        if (k == n) v += 1.0f - theta;
        __nv_bfloat16 hi, lo;
        bf16split(v, hi, lo);
        wh[i] = hi; wl[i] = lo;
    }
}

// ---------------- graph preprocessing ----------------
__global__ void k_zero(int* cnt, int* cursor) {
    int i = blockIdx.x * blockDim.x + threadIdx.x;
    if (i < NN) { cnt[i] = 0; cursor[i] = 0; }
}

__global__ void k_hist(const int* __restrict__ row, int* __restrict__ cnt) {
    int i = blockIdx.x * blockDim.x + threadIdx.x;
    if (i < NE) atomicAdd(&cnt[row[i]], 1);
}

__global__ void k_dis(const int* __restrict__ cnt, float* __restrict__ dis) {
    int i = blockIdx.x * blockDim.x + threadIdx.x;
    if (i < NN) {
        int c = cnt[i];
        float dg = (c == 0) ? 1.0f : (float)c;
        dis[i] = rsqrtf(dg);
    }
}

__global__ void k_bsum(const int* __restrict__ cnt, int* __restrict__ bsum) {
    __shared__ int sm[256];
    const int b = blockIdx.x, t = threadIdx.x;
    int base = b * 1024;
    int s = 0;
    #pragma unroll
    for (int q = 0; q < 4; q++) {
        int i = base + q * 256 + t;
        if (i < NN) s += cnt[i];
    }
    sm[t] = s;
    __syncthreads();
    for (int off = 128; off > 0; off >>= 1) {
        if (t < off) sm[t] += sm[t + off];
        __syncthreads();
    }
    if (t == 0) bsum[b] = sm[0];
}

__global__ void k_bscan(const int* __restrict__ bsum, int* __restrict__ boff) {
    __shared__ int sm[128];
    int t = threadIdx.x;
    sm[t] = (t < SCAN_NB) ? bsum[t] : 0;
    __syncthreads();
    for (int off = 1; off < 128; off <<= 1) {
        int v = (t >= off) ? sm[t - off] : 0;
        __syncthreads();
        sm[t] += v;
        __syncthreads();
    }
    if (t < SCAN_NB) boff[t] = (t == 0) ? 0 : sm[t - 1];
}

__global__ void k_rowptr(const int* __restrict__ cnt, const int* __restrict__ boff,
                         int* __restrict__ rowptr) {
    __shared__ int sm[256];
    const int b = blockIdx.x, t = threadIdx.x;
    int base = b * 1024;
    int vals[4];
    int s = 0;
    #pragma unroll
    for (int q = 0; q < 4; q++) {
        int i = base + t * 4 + q;
        vals[q] = (i < NN) ? cnt[i] : 0;
        s += vals[q];
    }
    sm[t] = s;
    __syncthreads();
    for (int off = 1; off < 256; off <<= 1) {
        int v = (t >= off) ? sm[t - off] : 0;
        __syncthreads();
        sm[t] += v;
        __syncthreads();
    }
    int run = boff[b] + ((t == 0) ? 0 : sm[t - 1]);
    #pragma unroll
    for (int q = 0; q < 4; q++) {
        int i = base + t * 4 + q;
        if (i < NN) rowptr[i] = run;
        run += vals[q];
    }
    if (b == 0 && t == 0) rowptr[NN] = NE;
}

__global__ void k_scatter(const int* __restrict__ row, const int* __restrict__ col,
                          const int* __restrict__ rowptr, int* __restrict__ cursor,
                          const float* __restrict__ dis,
                          int* __restrict__ colw, float* __restrict__ eww) {
    int i = blockIdx.x * blockDim.x + threadIdx.x;
    if (i < NE) {
        int r = row[i], c = col[i];
        int pos = rowptr[r] + atomicAdd(&cursor[r], 1);
        colw[pos] = c;
        eww[pos] = dis[r] * dis[c];
    }
}

// ---------------- SpMM + AOR blend, output pre-split into bf16 hi/lo planes ----------------
__global__ void k_spmm(const float* __restrict__ h, const float* __restrict__ h0,
                       const float* __restrict__ s, const int* __restrict__ rowptr,
                       const int* __restrict__ colw, const float* __restrict__ eww,
                       __nv_bfloat16* __restrict__ suph, __nv_bfloat16* __restrict__ supl) {
    int wid = (blockIdx.x * blockDim.x + threadIdx.x) >> 5;
    int lane = threadIdx.x & 31;
    if (wid >= NN) return;
    int start = rowptr[wid], end = rowptr[wid + 1];
    float ax = 0.f, ay = 0.f, az = 0.f, aw = 0.f;
    for (int e0 = start; e0 < end; e0 += 32) {
        int n = end - e0; if (n > 32) n = 32;
        int c = 0; float w = 0.f;
        if (lane < n) { c = colw[e0 + lane]; w = eww[e0 + lane]; }
        for (int j = 0; j < n; j++) {
            int cj   = __shfl_sync(0xffffffffu, c, j);
            float wj = __shfl_sync(0xffffffffu, w, j);
            const float4 hv = *reinterpret_cast<const float4*>(h + (size_t)cj * HID + lane * 4);
            ax += wj * hv.x; ay += wj * hv.y; az += wj * hv.z; aw += wj * hv.w;
        }
    }
    float sr = s[wid];
    float om = 1.0f - sr;
    const float4 h0v = *reinterpret_cast<const float4*>(h0 + (size_t)wid * HID + lane * 4);
    float vx = om * ax + sr * h0v.x;
    float vy = om * ay + sr * h0v.y;
    float vz = om * az + sr * h0v.z;
    float vw = om * aw + sr * h0v.w;
    unsigned int h01, l01, h23, l23;
    split2(make_float2(vx, vy), h01, l01);
    split2(make_float2(vz, vw), h23, l23);
    uint2 ho, lo2;
    ho.x = h01; ho.y = h23;
    lo2.x = l01; lo2.y = l23;
    *reinterpret_cast<uint2*>(suph + (size_t)wid * HID + lane * 4) = ho;
    *reinterpret_cast<uint2*>(supl + (size_t)wid * HID + lane * 4) = lo2;
}

// ---------------- 3xBF16 tensor-core GEMM (m16n8k16) + LN + gate epilogue ----------------
// PROJ : out = LN(x @ W + bias)   — A = fp32 x, split to bf16 hi/lo at fragment load
// else : out = LN(relu(A @ W'))  — A pre-split bf16 planes
// s_out = sigmoid(out @ q_w + q_b - 1)
// W always pre-split bf16, transposed [n][k]. A·B = Ah·Bh + Ah·Bl + Al·Bh.
#define KC 16                 // K per chunk = one m16n8k16
#define PITCH 24              // bf16 row pitch
#define APF 20                // fp32 A row pitch (PROJ)
#define PLANE_B (128 * PITCH * 2)       // 6144 bytes per bf16 plane-buffer
#define APLANE_B (128 * APF * 4)        // 10240 bytes per fp32 A buffer (PROJ, fits in A region)
#define O_AH 0
#define O_AL (2 * PLANE_B)
#define O_BH (4 * PLANE_B)
#define O_BL (6 * PLANE_B)
#define O_FLT (8 * PLANE_B)             // 49152: float region
#define SMEM_BYTES (O_FLT + (256 * 3 + 512) * 4)   // 54272

template<int K, bool PROJ>
__launch_bounds__(256, 2)
__global__ void k_gemm_tc(const __nv_bfloat16* __restrict__ Ah, const __nv_bfloat16* __restrict__ Al,
                          const float* __restrict__ Ax,
                          const __nv_bfloat16* __restrict__ Wh, const __nv_bfloat16* __restrict__ Wl,
                          const float* __restrict__ bias,
                          const float* __restrict__ gamma, const float* __restrict__ beta,
                          const float* __restrict__ qw, const float* __restrict__ qb,
                          float* __restrict__ out, float* __restrict__ s_out) {
    constexpr int NK = K / KC;
    extern __shared__ char smc[];
    float* fl  = (float*)(smc + O_FLT);
    float* stS = fl;
    float* stQ = fl + 256;
    float* stG = fl + 512;
    float* gsm = fl + 768;
    float* besm = gsm + 128;
    float* qsm  = gsm + 256;
    float* bism = gsm + 384;

    const int tid = threadIdx.x;
    const int lane = tid & 31;
    const int warp = tid >> 5;
    const int wm = warp & 3;          // rows wm*32
    const int wn = warp >> 2;         // cols wn*64
    const int g  = lane >> 2;
    const int t  = lane & 3;
    const int r0 = blockIdx.x * 128;
    const float qbv = qb[0];

    if (tid < 128) {
        gsm[tid]  = gamma[tid];
        besm[tid] = beta[tid];
        qsm[tid]  = qw[tid];
        bism[tid] = PROJ ? bias[tid] : 0.f;
    }

    // cp.async mappings
    const int crow = tid >> 1, chalf = tid & 1;   // bf16 planes: 1 chunk/thread/plane
    const int xrow0 = tid >> 2, xq0 = tid & 3;    // PROJ fp32 A: 2 chunks/thread
    const int xrow1 = (tid + 256) >> 2, xq1 = (tid + 256) & 3;

    auto issue = [&](int kt, int buf) {
        unsigned int d;
        if (PROJ) {
            int sz0 = (r0 + xrow0 < NN) ? 16 : 0;
            int sz1 = (r0 + xrow1 < NN) ? 16 : 0;
            d = (unsigned int)__cvta_generic_to_shared(smc + O_AH + buf * APLANE_B + xrow0 * (APF * 4) + xq0 * 16);
            cp_async16(d, Ax + (size_t)(r0 + xrow0) * K + kt + xq0 * 4, sz0);
            d = (unsigned int)__cvta_generic_to_shared(smc + O_AH + buf * APLANE_B + xrow1 * (APF * 4) + xq1 * 16);
            cp_async16(d, Ax + (size_t)(r0 + xrow1) * K + kt + xq1 * 4, sz1);
        } else {
            const int dof = crow * (PITCH * 2) + chalf * 16;
            const int soff = kt + chalf * 8;
            int szA = (r0 + crow < NN) ? 16 : 0;
            d = (unsigned int)__cvta_generic_to_shared(smc + O_AH + buf * PLANE_B + dof);
            cp_async16(d, Ah + (size_t)(r0 + crow) * K + soff, szA);
            d = (unsigned int)__cvta_generic_to_shared(smc + O_AL + buf * PLANE_B + dof);
            cp_async16(d, Al + (size_t)(r0 + crow) * K + soff, szA);
        }
        {
            const int dof = crow * (PITCH * 2) + chalf * 16;
            const int soff = kt + chalf * 8;
            d = (unsigned int)__cvta_generic_to_shared(smc + O_BH + buf * PLANE_B + dof);
            cp_async16(d, Wh + (size_t)crow * K + soff, 16);
            d = (unsigned int)__cvta_generic_to_shared(smc + O_BL + buf * PLANE_B + dof);
            cp_async16(d, Wl + (size_t)crow * K + soff, 16);
        }
        asm volatile("cp.async.commit_group;\n");
    };

    float acc[2][8][4];
    #pragma unroll
    for (int mt = 0; mt < 2; mt++)
        #pragma unroll
        for (int nt = 0; nt < 8; nt++)
            #pragma unroll
            for (int q = 0; q < 4; q++) acc[mt][nt][q] = 0.f;

    issue(0, 0);

    #pragma unroll
    for (int i = 0; i < NK; i++) {
        if (i + 1 < NK) {
            issue((i + 1) * KC, (i + 1) & 1);
            asm volatile("cp.async.wait_group 1;\n");
        } else {
            asm volatile("cp.async.wait_group 0;\n");
        }
        __syncthreads();

        unsigned int afh[2][4], afl[2][4];
        if (PROJ) {
            const float* af32 = (const float*)(smc + O_AH + (i & 1) * APLANE_B);
            #pragma unroll
            for (int mt = 0; mt < 2; mt++) {
                const int rA = (wm * 32 + mt * 16 + g) * APF;
                const int rB = rA + 8 * APF;
                float2 p0 = *(const float2*)&af32[rA + 2 * t];
                float2 p1 = *(const float2*)&af32[rB + 2 * t];
                float2 p2 = *(const float2*)&af32[rA + 8 + 2 * t];
                float2 p3 = *(const float2*)&af32[rB + 8 + 2 * t];
                split2(p0, afh[mt][0], afl[mt][0]);
                split2(p1, afh[mt][1], afl[mt][1]);
                split2(p2, afh[mt][2], afl[mt][2]);
                split2(p3, afh[mt][3], afl[mt][3]);
            }
        } else {
            const int bo = (i & 1) * PLANE_B;
            const __nv_bfloat16* ash = (const __nv_bfloat16*)(smc + O_AH + bo);
            const __nv_bfloat16* asl = (const __nv_bfloat16*)(smc + O_AL + bo);
            #pragma unroll
            for (int mt = 0; mt < 2; mt++) {
                const int r1 = (wm * 32 + mt * 16 + g) * PITCH;
                const int r2 = r1 + 8 * PITCH;
                afh[mt][0] = *(const unsigned int*)&ash[r1 + 2 * t];
                afh[mt][1] = *(const unsigned int*)&ash[r2 + 2 * t];
                afh[mt][2] = *(const unsigned int*)&ash[r1 + 8 + 2 * t];
                afh[mt][3] = *(const unsigned int*)&ash[r2 + 8 + 2 * t];
                afl[mt][0] = *(const unsigned int*)&asl[r1 + 2 * t];
                afl[mt][1] = *(const unsigned int*)&asl[r2 + 2 * t];
                afl[mt][2] = *(const unsigned int*)&asl[r1 + 8 + 2 * t];
                afl[mt][3] = *(const unsigned int*)&asl[r2 + 8 + 2 * t];
            }
        }
        const int bo = (i & 1) * PLANE_B;
        const __nv_bfloat16* bsh = (const __nv_bfloat16*)(smc + O_BH + bo);
        const __nv_bfloat16* bsl = (const __nv_bfloat16*)(smc + O_BL + bo);
        unsigned int bfh[8][2], bfl[8][2];
        #pragma unroll
        for (int nt = 0; nt < 8; nt++) {
            const int nb = (wn * 64 + nt * 8 + g) * PITCH;
            bfh[nt][0] = *(const unsigned int*)&bsh[nb + 2 * t];
            bfh[nt][1] = *(const unsigned int*)&bsh[nb + 8 + 2 * t];
            bfl[nt][0] = *(const unsigned int*)&bsl[nb + 2 * t];
            bfl[nt][1] = *(const unsigned int*)&bsl[nb + 8 + 2 * t];
        }
        #pragma unroll
        for (int mt = 0; mt < 2; mt++)
            #pragma unroll
            for (int nt = 0; nt < 8; nt++) {
                mma_bf16(acc[mt][nt], afh[mt], bfl[nt]);   // hi*lo
                mma_bf16(acc[mt][nt], afl[mt], bfh[nt]);   // lo*hi
                mma_bf16(acc[mt][nt], afh[mt], bfh[nt]);   // hi*hi (largest last)
            }
        __syncthreads();
    }

    // ---- epilogue in fragment layout ----
    float vsum[2][2], vsq[2][2];
    #pragma unroll
    for (int mt = 0; mt < 2; mt++)
        #pragma unroll
        for (int hf = 0; hf < 2; hf++) { vsum[mt][hf] = 0.f; vsq[mt][hf] = 0.f; }

    #pragma unroll
    for (int mt = 0; mt < 2; mt++)
        #pragma unroll
        for (int nt = 0; nt < 8; nt++) {
            int c0 = wn * 64 + nt * 8 + 2 * t;
            #pragma unroll
            for (int q = 0; q < 4; q++) {
                int col = c0 + (q & 1);
                float v = acc[mt][nt][q];
                v = PROJ ? (v + bism[col]) : fmaxf(v, 0.f);
                acc[mt][nt][q] = v;
                int hf = q >> 1;
                vsum[mt][hf] += v;
                vsq[mt][hf]  += v * v;
            }
        }

    #pragma unroll
    for (int off = 1; off <= 2; off <<= 1)
        #pragma unroll
        for (int mt = 0; mt < 2; mt++)
            #pragma unroll
            for (int hf = 0; hf < 2; hf++) {
                vsum[mt][hf] += __shfl_xor_sync(0xffffffffu, vsum[mt][hf], off);
                vsq[mt][hf]  += __shfl_xor_sync(0xffffffffu, vsq[mt][hf],  off);
            }

    if (t == 0) {
        #pragma unroll
        for (int mt = 0; mt < 2; mt++)
            #pragma unroll
            for (int hf = 0; hf < 2; hf++) {
                int rl = wm * 32 + mt * 16 + g + hf * 8;
                stS[wn * 128 + rl] = vsum[mt][hf];
                stQ[wn * 128 + rl] = vsq[mt][hf];
            }
    }
    __syncthreads();

    float mu[2][2], rs[2][2];
    #pragma unroll
    for (int mt = 0; mt < 2; mt++)
        #pragma unroll
        for (int hf = 0; hf < 2; hf++) {
            int rl = wm * 32 + mt * 16 + g + hf * 8;
            float sm = stS[rl] + stS[128 + rl];
            float sq = stQ[rl] + stQ[128 + rl];
            float m = sm * (1.0f / 128.0f);
            float var = sq * (1.0f / 128.0f) - m * m;
            var = fmaxf(var, 0.f);
            mu[mt][hf] = m;
            rs[mt][hf] = rsqrtf(var + LN_EPS);
        }

    float gp[2][2];
    #pragma unroll
    for (int mt = 0; mt < 2; mt++)
        #pragma unroll
        for (int hf = 0; hf < 2; hf++) gp[mt][hf] = 0.f;

    #pragma unroll
    for (int mt = 0; mt < 2; mt++)
        #pragma unroll
        for (int nt = 0; nt < 8; nt++) {
            int c0 = wn * 64 + nt * 8 + 2 * t;
            #pragma unroll
            for (int hf = 0; hf < 2; hf++) {
                float o0 = gsm[c0]     * (acc[mt][nt][hf * 2 + 0] - mu[mt][hf]) * rs[mt][hf] + besm[c0];
                float o1 = gsm[c0 + 1] * (acc[mt][nt][hf * 2 + 1] - mu[mt][hf]) * rs[mt][hf] + besm[c0 + 1];
                gp[mt][hf] += o0 * qsm[c0] + o1 * qsm[c0 + 1];
                int r = r0 + wm * 32 + mt * 16 + g + hf * 8;
                if (r < NN) {
                    float2 o2 = make_float2(o0, o1);
                    *reinterpret_cast<float2*>(out + (size_t)r * HID + c0) = o2;
                }
            }
        }

    #pragma unroll
    for (int off = 1; off <= 2; off <<= 1)
        #pragma unroll
        for (int mt = 0; mt < 2; mt++)
            #pragma unroll
            for (int hf = 0; hf < 2; hf++)
                gp[mt][hf] += __shfl_xor_sync(0xffffffffu, gp[mt][hf], off);

    if (t == 0) {
        #pragma unroll
        for (int mt = 0; mt < 2; mt++)
            #pragma unroll
            for (int hf = 0; hf < 2; hf++) {
                int rl = wm * 32 + mt * 16 + g + hf * 8;
                stG[wn * 128 + rl] = gp[mt][hf];
            }
    }
    __syncthreads();

    if (wn == 0 && t == 0) {
        #pragma unroll
        for (int mt = 0; mt < 2; mt++)
            #pragma unroll
            for (int hf = 0; hf < 2; hf++) {
                int rl = wm * 32 + mt * 16 + g + hf * 8;
                int r = r0 + rl;
                if (r < NN) {
                    float z = stG[rl] + stG[128 + rl] + qbv - 1.0f;
                    s_out[r] = 1.0f / (1.0f + expf(-z));
                }
            }
    }
}

// ---------------- classifier: out = h @ cls_w + cls_b ----------------
__global__ void k_cls(const float* __restrict__ h, const float* __restrict__ cw,
                      const float* __restrict__ cb, float* __restrict__ out) {
    __shared__ float wsm[HID * OUTD];
    __shared__ float bsm[OUTD];
    for (int i = threadIdx.x; i < HID * OUTD; i += blockDim.x) wsm[i] = cw[i];
    if (threadIdx.x < OUTD) bsm[threadIdx.x] = cb[threadIdx.x];
    __syncthreads();

    int wid = (blockIdx.x * blockDim.x + threadIdx.x) >> 5;
    int lane = threadIdx.x & 31;
    if (wid >= NN) return;
    const float4 hv = *reinterpret_cast<const float4*>(h + (size_t)wid * HID + lane * 4);
    float hvv[4] = {hv.x, hv.y, hv.z, hv.w};
    float p[OUTD];
    #pragma unroll
    for (int j = 0; j < OUTD; j++) p[j] = 0.f;
    #pragma unroll
    for (int tq = 0; tq < 4; tq++) {
        int k = lane * 4 + tq;
        #pragma unroll
        for (int j = 0; j < OUTD; j++) p[j] += hvv[tq] * wsm[k * OUTD + j];
    }
    #pragma unroll
    for (int off = 16; off > 0; off >>= 1)
        #pragma unroll
        for (int j = 0; j < OUTD; j++) p[j] += __shfl_xor_sync(0xffffffffu, p[j], off);
    if (lane == 0) {
        #pragma unroll
        for (int j = 0; j < OUTD; j++) out[(size_t)wid * OUTD + j] = p[j] + bsm[j];
    }
}

// ---------------- launch ----------------
extern "C" void kernel_launch(void* const* d_in, const int* in_sizes, int n_in,
                              void* d_out, int out_size) {
    const float* x      = (const float*)d_in[0];
    const int*   ei     = (const int*)d_in[1];
    const float* W_proj = (const float*)d_in[2];
    const float* b_proj = (const float*)d_in[3];
    const float* gamma  = (const float*)d_in[4];
    const float* beta   = (const float*)d_in[5];
    const float* q_w    = (const float*)d_in[6];
    const float* q_b    = (const float*)d_in[7];
    const float* conv_w = (const float*)d_in[8];
    const float* cls_w  = (const float*)d_in[9];
    const float* cls_b  = (const float*)d_in[10];
    float* out = (float*)d_out;

    const int* row = ei;
    const int* col = ei + NE;

    float *h0, *h, *s, *dis, *eww;
    __nv_bfloat16 *suph, *supl, *wmh, *wml, *wph, *wpl;
    int *cnt, *cursor, *rowptr, *colw, *bsum, *boff;
    cudaGetSymbolAddress((void**)&h0, g_h0);
    cudaGetSymbolAddress((void**)&h, g_h);
    cudaGetSymbolAddress((void**)&suph, g_suph);
    cudaGetSymbolAddress((void**)&supl, g_supl);
    cudaGetSymbolAddress((void**)&s, g_s);
    cudaGetSymbolAddress((void**)&dis, g_dis);
    cudaGetSymbolAddress((void**)&cnt, g_cnt);
    cudaGetSymbolAddress((void**)&cursor, g_cursor);
    cudaGetSymbolAddress((void**)&rowptr, g_rowptr);
    cudaGetSymbolAddress((void**)&colw, g_colw);
    cudaGetSymbolAddress((void**)&eww, g_eww);
    cudaGetSymbolAddress((void**)&bsum, g_bsum);
    cudaGetSymbolAddress((void**)&boff, g_boff);
    cudaGetSymbolAddress((void**)&wmh, g_wmodh);
    cudaGetSymbolAddress((void**)&wml, g_wmodl);
    cudaGetSymbolAddress((void**)&wph, g_wprojh);
    cudaGetSymbolAddress((void**)&wpl, g_wprojl);

    cudaFuncSetAttribute(k_gemm_tc<IND, true>,
                         cudaFuncAttributeMaxDynamicSharedMemorySize, SMEM_BYTES);
    cudaFuncSetAttribute(k_gemm_tc<HID, false>,
                         cudaFuncAttributeMaxDynamicSharedMemorySize, SMEM_BYTES);

    const int TB = 256;
    const int gN  = (NN + TB - 1) / TB;
    const int gE  = (NE + TB - 1) / TB;
    const int gW  = (NN * 32 + TB - 1) / TB;    // warp-per-row grids
    const int gG  = (NN + 127) / 128;           // gemm grid (782)

    // Fork a side stream so the CSR build overlaps the proj GEMM chain.
    // (host-side objects only; intentionally retained — see R12 notes)
    cudaStream_t s1;
    cudaStreamCreateWithFlags(&s1, cudaStreamNonBlocking);
    cudaEvent_t evF, evJ;
    cudaEventCreateWithFlags(&evF, cudaEventDisableTiming);
    cudaEventCreateWithFlags(&evJ, cudaEventDisableTiming);

    cudaEventRecord(evF, 0);
    cudaStreamWaitEvent(s1, evF, 0);

    // branch B (side stream): CSR build + layer-weight prep
    k_zero<<<gN, TB, 0, s1>>>(cnt, cursor);                                   // 0
    k_hist<<<gE, TB, 0, s1>>>(row, cnt);                                      // 1
    // branch A (main stream): proj weights + proj GEMM (in-kernel x split)
    k_prepproj<<<(IND * HID + 255) / 256, 256>>>(W_proj, wph, wpl);           // 2
    k_gemm_tc<IND, true><<<gG, 256, SMEM_BYTES>>>(nullptr, nullptr, x, wph, wpl,
                                                  b_proj, gamma, beta, q_w, q_b, h0, s); // 3
    k_dis<<<gN, TB, 0, s1>>>(cnt, dis);                                       // 4
    k_bsum<<<SCAN_NB, 256, 0, s1>>>(cnt, bsum);                               // 5
    k_bscan<<<1, 128, 0, s1>>>(bsum, boff);                                   // 6
    k_rowptr<<<SCAN_NB, 256, 0, s1>>>(cnt, boff, rowptr);                     // 7
    k_scatter<<<gE, TB, 0, s1>>>(row, col, rowptr, cursor, dis, colw, eww);   // 8
    k_prepw<<<(NL * HID * HID + 255) / 256, 256, 0, s1>>>(conv_w, wmh, wml);  // 9

    cudaEventRecord(evJ, s1);
    cudaStreamWaitEvent(0, evJ, 0);

    const float* hcur = h0;
    for (int i = 0; i < NL; i++) {
        k_spmm<<<gW, TB>>>(hcur, h0, s, rowptr, colw, eww, suph, supl);
        k_gemm_tc<HID, false><<<gG, 256, SMEM_BYTES>>>(suph, supl, nullptr,
                                                       wmh + (size_t)i * HID * HID,
                                                       wml + (size_t)i * HID * HID,
                                                       nullptr, gamma, beta, q_w, q_b, h, s);
        hcur = h;
    }

    k_cls<<<gW, TB>>>(hcur, cls_w, cls_b, out);
}

// round 17
// speedup vs baseline: 1.2685x; 1.0265x over previous
#include <cuda_runtime.h>
#include <cuda_bf16.h>
#include <stdint.h>
#include <math.h>

#define NN   100000
#define NE   1600000
#define IND  256
#define HID  128
#define NL   4
#define OUTD 7
#define LN_EPS 1e-5f
#define SCAN_NB ((NN + 1023) / 1024)   // 98

// ---------------- scratch (device globals: no allocation allowed) ----------------
__device__ float g_h0[(size_t)NN * HID];
__device__ float g_h [(size_t)NN * HID];
__device__ __nv_bfloat16 g_suph[(size_t)NN * HID];
__device__ __nv_bfloat16 g_supl[(size_t)NN * HID];
__device__ float g_s[NN];
__device__ float g_dis[NN];
__device__ int   g_cnt[NN];
__device__ int   g_cursor[NN];
__device__ int   g_rowptr[NN + 1];
__device__ int   g_colw[NE];
__device__ float g_eww[NE];
__device__ int   g_bsum[SCAN_NB + 32];
__device__ int   g_boff[SCAN_NB + 32];
__device__ __nv_bfloat16 g_wmodh[(size_t)NL * HID * HID];   // [l][n][k]
__device__ __nv_bfloat16 g_wmodl[(size_t)NL * HID * HID];
__device__ __nv_bfloat16 g_wprojh[(size_t)HID * IND];       // [n][k]
__device__ __nv_bfloat16 g_wprojl[(size_t)HID * IND];

// ---------------- helpers ----------------
__device__ __forceinline__ void bf16split(float v, __nv_bfloat16& hi, __nv_bfloat16& lo) {
    hi = __float2bfloat16(v);
    lo = __float2bfloat16(v - __bfloat162float(hi));
}

// split a float2 (two consecutive k values) into packed bf16x2 hi and lo words
__device__ __forceinline__ void split2(float2 p, unsigned int& hi, unsigned int& lo) {
    __nv_bfloat16 h0, l0, h1, l1;
    bf16split(p.x, h0, l0);
    bf16split(p.y, h1, l1);
    __nv_bfloat162 hp = __halves2bfloat162(h0, h1);
    __nv_bfloat162 lp = __halves2bfloat162(l0, l1);
    hi = *reinterpret_cast<unsigned int*>(&hp);
    lo = *reinterpret_cast<unsigned int*>(&lp);
}

__device__ __forceinline__ void mma_bf16(float* d, const unsigned int* a, const unsigned int* b) {
    asm volatile(
        "mma.sync.aligned.m16n8k16.row.col.f32.bf16.bf16.f32 "
        "{%0,%1,%2,%3}, {%4,%5,%6,%7}, {%8,%9}, {%0,%1,%2,%3};\n"
        : "+f"(d[0]), "+f"(d[1]), "+f"(d[2]), "+f"(d[3])
        : "r"(a[0]), "r"(a[1]), "r"(a[2]), "r"(a[3]), "r"(b[0]), "r"(b[1]));
}

__device__ __forceinline__ void ldsm4(unsigned int* r, unsigned int addr) {
    asm volatile("ldmatrix.sync.aligned.m8n8.x4.shared.b16 {%0,%1,%2,%3}, [%4];"
                 : "=r"(r[0]), "=r"(r[1]), "=r"(r[2]), "=r"(r[3]) : "r"(addr));
}

__device__ __forceinline__ void cp_async16(unsigned int smem_addr, const void* gptr, int src_sz) {
    asm volatile("cp.async.cg.shared.global [%0], [%1], 16, %2;\n"
                 :: "r"(smem_addr), "l"(gptr), "r"(src_sz));
}

// ---------------- weight prep ----------------
// W_proj [k][n] -> transposed bf16 planes [n][k]
__global__ void k_prepproj(const float* __restrict__ wp,
                           __nv_bfloat16* __restrict__ wh, __nv_bfloat16* __restrict__ wl) {
    int i = blockIdx.x * blockDim.x + threadIdx.x;
    if (i < IND * HID) {
        int n = i / IND, k = i - n * IND;
        float v = wp[(size_t)k * HID + n];
        __nv_bfloat16 hi, lo;
        bf16split(v, hi, lo);
        wh[i] = hi; wl[i] = lo;
    }
}

// W'[l] = theta_l*conv_w[l] + (1-theta_l)*I, transposed bf16 planes [l][n][k]
__global__ void k_prepw(const float* __restrict__ conv_w,
                        __nv_bfloat16* __restrict__ wh, __nv_bfloat16* __restrict__ wl) {
    int i = blockIdx.x * blockDim.x + threadIdx.x;
    if (i < NL * HID * HID) {
        int l = i / (HID * HID);
        int rc = i - l * (HID * HID);
        int n = rc >> 7, k = rc & 127;
        float theta = 0.5f / (float)(l + 1);
        float v = theta * conv_w[(size_t)l * HID * HID + k * HID + n];
        if (k == n) v += 1.0f - theta;
        __nv_bfloat16 hi, lo;
        bf16split(v, hi, lo);
        wh[i] = hi; wl[i] = lo;
    }
}

// ---------------- graph preprocessing ----------------
__global__ void k_zero(int* cnt, int* cursor) {
    int i = blockIdx.x * blockDim.x + threadIdx.x;
    if (i < NN) { cnt[i] = 0; cursor[i] = 0; }
}

__global__ void k_hist(const int* __restrict__ row, int* __restrict__ cnt) {
    int i = blockIdx.x * blockDim.x + threadIdx.x;
    if (i < NE) atomicAdd(&cnt[row[i]], 1);
}

__global__ void k_dis(const int* __restrict__ cnt, float* __restrict__ dis) {
    int i = blockIdx.x * blockDim.x + threadIdx.x;
    if (i < NN) {
        int c = cnt[i];
        float dg = (c == 0) ? 1.0f : (float)c;
        dis[i] = rsqrtf(dg);
    }
}

__global__ void k_bsum(const int* __restrict__ cnt, int* __restrict__ bsum) {
    __shared__ int sm[256];
    const int b = blockIdx.x, t = threadIdx.x;
    int base = b * 1024;
    int s = 0;
    #pragma unroll
    for (int q = 0; q < 4; q++) {
        int i = base + q * 256 + t;
        if (i < NN) s += cnt[i];
    }
    sm[t] = s;
    __syncthreads();
    for (int off = 128; off > 0; off >>= 1) {
        if (t < off) sm[t] += sm[t + off];
        __syncthreads();
    }
    if (t == 0) bsum[b] = sm[0];
}

__global__ void k_bscan(const int* __restrict__ bsum, int* __restrict__ boff) {
    __shared__ int sm[128];
    int t = threadIdx.x;
    sm[t] = (t < SCAN_NB) ? bsum[t] : 0;
    __syncthreads();
    for (int off = 1; off < 128; off <<= 1) {
        int v = (t >= off) ? sm[t - off] : 0;
        __syncthreads();
        sm[t] += v;
        __syncthreads();
    }
    if (t < SCAN_NB) boff[t] = (t == 0) ? 0 : sm[t - 1];
}

__global__ void k_rowptr(const int* __restrict__ cnt, const int* __restrict__ boff,
                         int* __restrict__ rowptr) {
    __shared__ int sm[256];
    const int b = blockIdx.x, t = threadIdx.x;
    int base = b * 1024;
    int vals[4];
    int s = 0;
    #pragma unroll
    for (int q = 0; q < 4; q++) {
        int i = base + t * 4 + q;
        vals[q] = (i < NN) ? cnt[i] : 0;
        s += vals[q];
    }
    sm[t] = s;
    __syncthreads();
    for (int off = 1; off < 256; off <<= 1) {
        int v = (t >= off) ? sm[t - off] : 0;
        __syncthreads();
        sm[t] += v;
        __syncthreads();
    }
    int run = boff[b] + ((t == 0) ? 0 : sm[t - 1]);
    #pragma unroll
    for (int q = 0; q < 4; q++) {
        int i = base + t * 4 + q;
        if (i < NN) rowptr[i] = run;
        run += vals[q];
    }
    if (b == 0 && t == 0) rowptr[NN] = NE;
}

__global__ void k_scatter(const int* __restrict__ row, const int* __restrict__ col,
                          const int* __restrict__ rowptr, int* __restrict__ cursor,
                          const float* __restrict__ dis,
                          int* __restrict__ colw, float* __restrict__ eww) {
    int i = blockIdx.x * blockDim.x + threadIdx.x;
    if (i < NE) {
        int r = row[i], c = col[i];
        int pos = rowptr[r] + atomicAdd(&cursor[r], 1);
        colw[pos] = c;
        eww[pos] = dis[r] * dis[c];
    }
}

// ---------------- SpMM + AOR blend, output pre-split into bf16 hi/lo planes ----------------
__global__ void k_spmm(const float* __restrict__ h, const float* __restrict__ h0,
                       const float* __restrict__ s, const int* __restrict__ rowptr,
                       const int* __restrict__ colw, const float* __restrict__ eww,
                       __nv_bfloat16* __restrict__ suph, __nv_bfloat16* __restrict__ supl) {
    int wid = (blockIdx.x * blockDim.x + threadIdx.x) >> 5;
    int lane = threadIdx.x & 31;
    if (wid >= NN) return;
    int start = rowptr[wid], end = rowptr[wid + 1];
    float ax = 0.f, ay = 0.f, az = 0.f, aw = 0.f;
    for (int e0 = start; e0 < end; e0 += 32) {
        int n = end - e0; if (n > 32) n = 32;
        int c = 0; float w = 0.f;
        if (lane < n) { c = colw[e0 + lane]; w = eww[e0 + lane]; }
        for (int j = 0; j < n; j++) {
            int cj   = __shfl_sync(0xffffffffu, c, j);
            float wj = __shfl_sync(0xffffffffu, w, j);
            const float4 hv = *reinterpret_cast<const float4*>(h + (size_t)cj * HID + lane * 4);
            ax += wj * hv.x; ay += wj * hv.y; az += wj * hv.z; aw += wj * hv.w;
        }
    }
    float sr = s[wid];
    float om = 1.0f - sr;
    const float4 h0v = *reinterpret_cast<const float4*>(h0 + (size_t)wid * HID + lane * 4);
    float vx = om * ax + sr * h0v.x;
    float vy = om * ay + sr * h0v.y;
    float vz = om * az + sr * h0v.z;
    float vw = om * aw + sr * h0v.w;
    unsigned int h01, l01, h23, l23;
    split2(make_float2(vx, vy), h01, l01);
    split2(make_float2(vz, vw), h23, l23);
    uint2 ho, lo2;
    ho.x = h01; ho.y = h23;
    lo2.x = l01; lo2.y = l23;
    *reinterpret_cast<uint2*>(suph + (size_t)wid * HID + lane * 4) = ho;
    *reinterpret_cast<uint2*>(supl + (size_t)wid * HID + lane * 4) = lo2;
}

// ---------------- 3xBF16 tensor-core GEMM (m16n8k16) + LN + gate epilogue ----------------
// PROJ : out = LN(x @ W + bias)   — A = fp32 x, split to bf16 hi/lo at fragment load
// else : out = LN(relu(A @ W'))  — A pre-split bf16 planes, fragments via ldmatrix
// s_out = sigmoid(out @ q_w + q_b - 1)
// W always pre-split bf16, transposed [n][k]; fragments via ldmatrix.
// A·B = Ah·Bh + Ah·Bl + Al·Bh.
#define KC 16                 // K per chunk = one m16n8k16
#define PITCH 24              // bf16 row pitch (48 B rows -> ldmatrix conflict-free)
#define APF 20                // fp32 A row pitch (PROJ)
#define PLANE_B (128 * PITCH * 2)       // 6144 bytes per bf16 plane-buffer
#define APLANE_B (128 * APF * 4)        // 10240 bytes per fp32 A buffer (PROJ)
#define O_AH 0
#define O_AL (2 * PLANE_B)
#define O_BH (4 * PLANE_B)
#define O_BL (6 * PLANE_B)
#define O_FLT (8 * PLANE_B)             // 49152: float region
#define SMEM_BYTES (O_FLT + (256 * 3 + 512) * 4)   // 54272

template<int K, bool PROJ>
__launch_bounds__(256, 2)
__global__ void k_gemm_tc(const __nv_bfloat16* __restrict__ Ah, const __nv_bfloat16* __restrict__ Al,
                          const float* __restrict__ Ax,
                          const __nv_bfloat16* __restrict__ Wh, const __nv_bfloat16* __restrict__ Wl,
                          const float* __restrict__ bias,
                          const float* __restrict__ gamma, const float* __restrict__ beta,
                          const float* __restrict__ qw, const float* __restrict__ qb,
                          float* __restrict__ out, float* __restrict__ s_out) {
    constexpr int NK = K / KC;
    extern __shared__ char smc[];
    float* fl  = (float*)(smc + O_FLT);
    float* stS = fl;
    float* stQ = fl + 256;
    float* stG = fl + 512;
    float* gsm = fl + 768;
    float* besm = gsm + 128;
    float* qsm  = gsm + 256;
    float* bism = gsm + 384;

    const int tid = threadIdx.x;
    const int lane = tid & 31;
    const int warp = tid >> 5;
    const int wm = warp & 3;          // rows wm*32
    const int wn = warp >> 2;         // cols wn*64
    const int g  = lane >> 2;
    const int t  = lane & 3;
    const int r0 = blockIdx.x * 128;
    const float qbv = qb[0];

    if (tid < 128) {
        gsm[tid]  = gamma[tid];
        besm[tid] = beta[tid];
        qsm[tid]  = qw[tid];
        bism[tid] = PROJ ? bias[tid] : 0.f;
    }

    // cp.async mappings
    const int crow = tid >> 1, chalf = tid & 1;   // bf16 planes: 1 chunk/thread/plane
    const int xrow0 = tid >> 2, xq0 = tid & 3;    // PROJ fp32 A: 2 chunks/thread
    const int xrow1 = (tid + 256) >> 2, xq1 = (tid + 256) & 3;

    // ldmatrix per-lane address offsets
    const unsigned int sb = (unsigned int)__cvta_generic_to_shared(smc);
    const int lm = lane >> 3, lr = lane & 7;
    // B: 4 calls per plane; call q loads blocks (nt=2q,klo),(2q,khi),(2q+1,klo),(2q+1,khi)
    unsigned int bq[4];
    #pragma unroll
    for (int q = 0; q < 4; q++)
        bq[q] = (unsigned int)((wn * 64 + 16 * q + ((lm >> 1) << 3) + lr) * (PITCH * 2) + ((lm & 1) << 4));
    // A (layer): 1 call per (mt, plane); blocks (rlo,klo),(rhi,klo),(rlo,khi),(rhi,khi)
    unsigned int aq[2];
    #pragma unroll
    for (int mt = 0; mt < 2; mt++)
        aq[mt] = (unsigned int)((wm * 32 + mt * 16 + ((lm & 1) << 3) + lr) * (PITCH * 2) + ((lm >> 1) << 4));

    auto issue = [&](int kt, int buf) {
        unsigned int d;
        if (PROJ) {
            int sz0 = (r0 + xrow0 < NN) ? 16 : 0;
            int sz1 = (r0 + xrow1 < NN) ? 16 : 0;
            d = sb + O_AH + buf * APLANE_B + xrow0 * (APF * 4) + xq0 * 16;
            cp_async16(d, Ax + (size_t)(r0 + xrow0) * K + kt + xq0 * 4, sz0);
            d = sb + O_AH + buf * APLANE_B + xrow1 * (APF * 4) + xq1 * 16;
            cp_async16(d, Ax + (size_t)(r0 + xrow1) * K + kt + xq1 * 4, sz1);
        } else {
            const int dof = crow * (PITCH * 2) + chalf * 16;
            const int soff = kt + chalf * 8;
            int szA = (r0 + crow < NN) ? 16 : 0;
            d = sb + O_AH + buf * PLANE_B + dof;
            cp_async16(d, Ah + (size_t)(r0 + crow) * K + soff, szA);
            d = sb + O_AL + buf * PLANE_B + dof;
            cp_async16(d, Al + (size_t)(r0 + crow) * K + soff, szA);
        }
        {
            const int dof = crow * (PITCH * 2) + chalf * 16;
            const int soff = kt + chalf * 8;
            d = sb + O_BH + buf * PLANE_B + dof;
            cp_async16(d, Wh + (size_t)crow * K + soff, 16);
            d = sb + O_BL + buf * PLANE_B + dof;
            cp_async16(d, Wl + (size_t)crow * K + soff, 16);
        }
        asm volatile("cp.async.commit_group;\n");
    };

    float acc[2][8][4];
    #pragma unroll
    for (int mt = 0; mt < 2; mt++)
        #pragma unroll
        for (int nt = 0; nt < 8; nt++)
            #pragma unroll
            for (int q = 0; q < 4; q++) acc[mt][nt][q] = 0.f;

    issue(0, 0);

    #pragma unroll
    for (int i = 0; i < NK; i++) {
        asm volatile("cp.async.wait_group 0;\n");
        __syncthreads();
        if (i + 1 < NK) issue((i + 1) * KC, (i + 1) & 1);

        const int bo = (i & 1) * PLANE_B;
        unsigned int afh[2][4], afl[2][4];
        if (PROJ) {
            const float* af32 = (const float*)(smc + O_AH + (i & 1) * APLANE_B);
            #pragma unroll
            for (int mt = 0; mt < 2; mt++) {
                const int rA = (wm * 32 + mt * 16 + g) * APF;
                const int rB = rA + 8 * APF;
                float2 p0 = *(const float2*)&af32[rA + 2 * t];
                float2 p1 = *(const float2*)&af32[rB + 2 * t];
                float2 p2 = *(const float2*)&af32[rA + 8 + 2 * t];
                float2 p3 = *(const float2*)&af32[rB + 8 + 2 * t];
                split2(p0, afh[mt][0], afl[mt][0]);
                split2(p1, afh[mt][1], afl[mt][1]);
                split2(p2, afh[mt][2], afl[mt][2]);
                split2(p3, afh[mt][3], afl[mt][3]);
            }
        } else {
            const unsigned int aH = sb + O_AH + bo;
            const unsigned int aL = sb + O_AL + bo;
            #pragma unroll
            for (int mt = 0; mt < 2; mt++) {
                ldsm4(afh[mt], aH + aq[mt]);
                ldsm4(afl[mt], aL + aq[mt]);
            }
        }
        const unsigned int bH = sb + O_BH + bo;
        const unsigned int bL = sb + O_BL + bo;
        unsigned int bfh[8][2], bfl[8][2];
        #pragma unroll
        for (int q = 0; q < 4; q++) {
            unsigned int rr[4];
            ldsm4(rr, bH + bq[q]);
            bfh[2 * q][0] = rr[0]; bfh[2 * q][1] = rr[1];
            bfh[2 * q + 1][0] = rr[2]; bfh[2 * q + 1][1] = rr[3];
            ldsm4(rr, bL + bq[q]);
            bfl[2 * q][0] = rr[0]; bfl[2 * q][1] = rr[1];
            bfl[2 * q + 1][0] = rr[2]; bfl[2 * q + 1][1] = rr[3];
        }
        #pragma unroll
        for (int mt = 0; mt < 2; mt++)
            #pragma unroll
            for (int nt = 0; nt < 8; nt++) {
                mma_bf16(acc[mt][nt], afh[mt], bfl[nt]);   // hi*lo
                mma_bf16(acc[mt][nt], afl[mt], bfh[nt]);   // lo*hi
                mma_bf16(acc[mt][nt], afh[mt], bfh[nt]);   // hi*hi (largest last)
            }
    }
    __syncthreads();

    // ---- epilogue in fragment layout ----
    float vsum[2][2], vsq[2][2];
    #pragma unroll
    for (int mt = 0; mt < 2; mt++)
        #pragma unroll
        for (int hf = 0; hf < 2; hf++) { vsum[mt][hf] = 0.f; vsq[mt][hf] = 0.f; }

    #pragma unroll
    for (int mt = 0; mt < 2; mt++)
        #pragma unroll
        for (int nt = 0; nt < 8; nt++) {
            int c0 = wn * 64 + nt * 8 + 2 * t;
            #pragma unroll
            for (int q = 0; q < 4; q++) {
                int col = c0 + (q & 1);
                float v = acc[mt][nt][q];
                v = PROJ ? (v + bism[col]) : fmaxf(v, 0.f);
                acc[mt][nt][q] = v;
                int hf = q >> 1;
                vsum[mt][hf] += v;
                vsq[mt][hf]  += v * v;
            }
        }

    #pragma unroll
    for (int off = 1; off <= 2; off <<= 1)
        #pragma unroll
        for (int mt = 0; mt < 2; mt++)
            #pragma unroll
            for (int hf = 0; hf < 2; hf++) {
                vsum[mt][hf] += __shfl_xor_sync(0xffffffffu, vsum[mt][hf], off);
                vsq[mt][hf]  += __shfl_xor_sync(0xffffffffu, vsq[mt][hf],  off);
            }

    if (t == 0) {
        #pragma unroll
        for (int mt = 0; mt < 2; mt++)
            #pragma unroll
            for (int hf = 0; hf < 2; hf++) {
                int rl = wm * 32 + mt * 16 + g + hf * 8;
                stS[wn * 128 + rl] = vsum[mt][hf];
                stQ[wn * 128 + rl] = vsq[mt][hf];
            }
    }
    __syncthreads();

    float mu[2][2], rs[2][2];
    #pragma unroll
    for (int mt = 0; mt < 2; mt++)
        #pragma unroll
        for (int hf = 0; hf < 2; hf++) {
            int rl = wm * 32 + mt * 16 + g + hf * 8;
            float sm = stS[rl] + stS[128 + rl];
            float sq = stQ[rl] + stQ[128 + rl];
            float m = sm * (1.0f / 128.0f);
            float var = sq * (1.0f / 128.0f) - m * m;
            var = fmaxf(var, 0.f);
            mu[mt][hf] = m;
            rs[mt][hf] = rsqrtf(var + LN_EPS);
        }

    float gp[2][2];
    #pragma unroll
    for (int mt = 0; mt < 2; mt++)
        #pragma unroll
        for (int hf = 0; hf < 2; hf++) gp[mt][hf] = 0.f;

    #pragma unroll
    for (int mt = 0; mt < 2; mt++)
        #pragma unroll
        for (int nt = 0; nt < 8; nt++) {
            int c0 = wn * 64 + nt * 8 + 2 * t;
            #pragma unroll
            for (int hf = 0; hf < 2; hf++) {
                float o0 = gsm[c0]     * (acc[mt][nt][hf * 2 + 0] - mu[mt][hf]) * rs[mt][hf] + besm[c0];
                float o1 = gsm[c0 + 1] * (acc[mt][nt][hf * 2 + 1] - mu[mt][hf]) * rs[mt][hf] + besm[c0 + 1];
                gp[mt][hf] += o0 * qsm[c0] + o1 * qsm[c0 + 1];
                int r = r0 + wm * 32 + mt * 16 + g + hf * 8;
                if (r < NN) {
                    float2 o2 = make_float2(o0, o1);
                    *reinterpret_cast<float2*>(out + (size_t)r * HID + c0) = o2;
                }
            }
        }

    #pragma unroll
    for (int off = 1; off <= 2; off <<= 1)
        #pragma unroll
        for (int mt = 0; mt < 2; mt++)
            #pragma unroll
            for (int hf = 0; hf < 2; hf++)
                gp[mt][hf] += __shfl_xor_sync(0xffffffffu, gp[mt][hf], off);

    if (t == 0) {
        #pragma unroll
        for (int mt = 0; mt < 2; mt++)
            #pragma unroll
            for (int hf = 0; hf < 2; hf++) {
                int rl = wm * 32 + mt * 16 + g + hf * 8;
                stG[wn * 128 + rl] = gp[mt][hf];
            }
    }
    __syncthreads();

    if (wn == 0 && t == 0) {
        #pragma unroll
        for (int mt = 0; mt < 2; mt++)
            #pragma unroll
            for (int hf = 0; hf < 2; hf++) {
                int rl = wm * 32 + mt * 16 + g + hf * 8;
                int r = r0 + rl;
                if (r < NN) {
                    float z = stG[rl] + stG[128 + rl] + qbv - 1.0f;
                    s_out[r] = 1.0f / (1.0f + expf(-z));
                }
            }
    }
}

// ---------------- classifier: out = h @ cls_w + cls_b ----------------
__global__ void k_cls(const float* __restrict__ h, const float* __restrict__ cw,
                      const float* __restrict__ cb, float* __restrict__ out) {
    __shared__ float wsm[HID * OUTD];
    __shared__ float bsm[OUTD];
    for (int i = threadIdx.x; i < HID * OUTD; i += blockDim.x) wsm[i] = cw[i];
    if (threadIdx.x < OUTD) bsm[threadIdx.x] = cb[threadIdx.x];
    __syncthreads();

    int wid = (blockIdx.x * blockDim.x + threadIdx.x) >> 5;
    int lane = threadIdx.x & 31;
    if (wid >= NN) return;
    const float4 hv = *reinterpret_cast<const float4*>(h + (size_t)wid * HID + lane * 4);
    float hvv[4] = {hv.x, hv.y, hv.z, hv.w};
    float p[OUTD];
    #pragma unroll
    for (int j = 0; j < OUTD; j++) p[j] = 0.f;
    #pragma unroll
    for (int tq = 0; tq < 4; tq++) {
        int k = lane * 4 + tq;
        #pragma unroll
        for (int j = 0; j < OUTD; j++) p[j] += hvv[tq] * wsm[k * OUTD + j];
    }
    #pragma unroll
    for (int off = 16; off > 0; off >>= 1)
        #pragma unroll
        for (int j = 0; j < OUTD; j++) p[j] += __shfl_xor_sync(0xffffffffu, p[j], off);
    if (lane == 0) {
        #pragma unroll
        for (int j = 0; j < OUTD; j++) out[(size_t)wid * OUTD + j] = p[j] + bsm[j];
    }
}

// ---------------- launch ----------------
extern "C" void kernel_launch(void* const* d_in, const int* in_sizes, int n_in,
                              void* d_out, int out_size) {
    const float* x      = (const float*)d_in[0];
    const int*   ei     = (const int*)d_in[1];
    const float* W_proj = (const float*)d_in[2];
    const float* b_proj = (const float*)d_in[3];
    const float* gamma  = (const float*)d_in[4];
    const float* beta   = (const float*)d_in[5];
    const float* q_w    = (const float*)d_in[6];
    const float* q_b    = (const float*)d_in[7];
    const float* conv_w = (const float*)d_in[8];
    const float* cls_w  = (const float*)d_in[9];
    const float* cls_b  = (const float*)d_in[10];
    float* out = (float*)d_out;

    const int* row = ei;
    const int* col = ei + NE;

    float *h0, *h, *s, *dis, *eww;
    __nv_bfloat16 *suph, *supl, *wmh, *wml, *wph, *wpl;
    int *cnt, *cursor, *rowptr, *colw, *bsum, *boff;
    cudaGetSymbolAddress((void**)&h0, g_h0);
    cudaGetSymbolAddress((void**)&h, g_h);
    cudaGetSymbolAddress((void**)&suph, g_suph);
    cudaGetSymbolAddress((void**)&supl, g_supl);
    cudaGetSymbolAddress((void**)&s, g_s);
    cudaGetSymbolAddress((void**)&dis, g_dis);
    cudaGetSymbolAddress((void**)&cnt, g_cnt);
    cudaGetSymbolAddress((void**)&cursor, g_cursor);
    cudaGetSymbolAddress((void**)&rowptr, g_rowptr);
    cudaGetSymbolAddress((void**)&colw, g_colw);
    cudaGetSymbolAddress((void**)&eww, g_eww);
    cudaGetSymbolAddress((void**)&bsum, g_bsum);
    cudaGetSymbolAddress((void**)&boff, g_boff);
    cudaGetSymbolAddress((void**)&wmh, g_wmodh);
    cudaGetSymbolAddress((void**)&wml, g_wmodl);
    cudaGetSymbolAddress((void**)&wph, g_wprojh);
    cudaGetSymbolAddress((void**)&wpl, g_wprojl);

    cudaFuncSetAttribute(k_gemm_tc<IND, true>,
                         cudaFuncAttributeMaxDynamicSharedMemorySize, SMEM_BYTES);
    cudaFuncSetAttribute(k_gemm_tc<HID, false>,
                         cudaFuncAttributeMaxDynamicSharedMemorySize, SMEM_BYTES);

    const int TB = 256;
    const int gN  = (NN + TB - 1) / TB;
    const int gE  = (NE + TB - 1) / TB;
    const int gW  = (NN * 32 + TB - 1) / TB;    // warp-per-row grids
    const int gG  = (NN + 127) / 128;           // gemm grid (782)

    // Fork a side stream so the CSR build overlaps the proj GEMM chain.
    // (host-side objects only; intentionally retained — see R12 notes)
    cudaStream_t s1;
    cudaStreamCreateWithFlags(&s1, cudaStreamNonBlocking);
    cudaEvent_t evF, evJ;
    cudaEventCreateWithFlags(&evF, cudaEventDisableTiming);
    cudaEventCreateWithFlags(&evJ, cudaEventDisableTiming);

    cudaEventRecord(evF, 0);
    cudaStreamWaitEvent(s1, evF, 0);

    // branch B (side stream): CSR build + layer-weight prep
    k_zero<<<gN, TB, 0, s1>>>(cnt, cursor);                                   // 0
    k_hist<<<gE, TB, 0, s1>>>(row, cnt);                                      // 1
    // branch A (main stream): proj weights + proj GEMM (in-kernel x split)
    k_prepproj<<<(IND * HID + 255) / 256, 256>>>(W_proj, wph, wpl);           // 2
    k_gemm_tc<IND, true><<<gG, 256, SMEM_BYTES>>>(nullptr, nullptr, x, wph, wpl,
                                                  b_proj, gamma, beta, q_w, q_b, h0, s); // 3
    k_dis<<<gN, TB, 0, s1>>>(cnt, dis);                                       // 4
    k_bsum<<<SCAN_NB, 256, 0, s1>>>(cnt, bsum);                               // 5
    k_bscan<<<1, 128, 0, s1>>>(bsum, boff);                                   // 6
    k_rowptr<<<SCAN_NB, 256, 0, s1>>>(cnt, boff, rowptr);                     // 7
    k_scatter<<<gE, TB, 0, s1>>>(row, col, rowptr, cursor, dis, colw, eww);   // 8
    k_prepw<<<(NL * HID * HID + 255) / 256, 256, 0, s1>>>(conv_w, wmh, wml);  // 9

    cudaEventRecord(evJ, s1);
    cudaStreamWaitEvent(0, evJ, 0);

    const float* hcur = h0;
    for (int i = 0; i < NL; i++) {
        k_spmm<<<gW, TB>>>(hcur, h0, s, rowptr, colw, eww, suph, supl);
        k_gemm_tc<HID, false><<<gG, 256, SMEM_BYTES>>>(suph, supl, nullptr,
                                                       wmh + (size_t)i * HID * HID,
                                                       wml + (size_t)i * HID * HID,
                                                       nullptr, gamma, beta, q_w, q_b, h, s);
        hcur = h;
    }

    k_cls<<<gW, TB>>>(hcur, cls_w, cls_b, out);
}